// round 10
// baseline (speedup 1.0000x reference)
#include <cuda_runtime.h>
#include <cstdint>

// Problem constants: B=64, S=512, A=8, D=128, C=1024
#define PB  64
#define PS  512
#define PA  8
#define PD  128

#define LEN_BLOCKS 64   // first LEN_BLOCKS blocks compute candidate_len
#define ITER 8          // candidates per warp
#define CPB  64         // candidates per block = 8 warps * ITER
#define STAGES 4        // cp.async pipeline depth

__device__ __forceinline__ void cpasync16(uint32_t dst_smem, const void* src) {
    asm volatile("cp.async.cg.shared.global [%0], [%1], 16;"
                 :: "r"(dst_smem), "l"(src));
}
__device__ __forceinline__ void cpcommit() {
    asm volatile("cp.async.commit_group;");
}
__device__ __forceinline__ void cpwait3() {
    asm volatile("cp.async.wait_group 3;");
}
__device__ __forceinline__ void cpwait0() {
    asm volatile("cp.async.wait_group 0;");
}

// ---------------------------------------------------------------------------
// blocks [0,64):  candidate_len per batch (independent role, reads inputs).
// blocks [64,..): gather — 8 warps x 8 candidates. Per warp: all 8 flat
//   indices computed up front (coalesced idx load + shuffles); repr rows are
//   staged into SMEM via cp.async (depth-4 groups) so load latency never
//   touches the register scoreboard; consume = LDS.128 -> mask -> STG.128.
// ---------------------------------------------------------------------------
__global__ void __launch_bounds__(256)
cand_kernel(const float*  __restrict__ word_repr,
            const int*    __restrict__ anchor_cls,
            const int*    __restrict__ anchor_loc,
            const int*    __restrict__ cand_idx,
            float*        __restrict__ out,
            long long off_label,
            long long off_mask,
            long long off_loc,
            long long off_len,
            long long off_scalar,   // -1 if absent
            float scalar_val,
            int BC, int C)
{
    if (blockIdx.x < LEN_BLOCKS) {
        // ---- len role ----
        __shared__ int rsm[8];
        int batch = blockIdx.x;
        int base  = batch * C;

        int sum = 0;
        for (int i = threadIdx.x; i < C; i += blockDim.x) {
            int c = base + i;
            int b = cand_idx[3 * c + 0];
            int w = cand_idx[3 * c + 1];
            int a = cand_idx[3 * c + 2];
            long long flat = (((long long)b * PS + w) * PA + a);
            int2 loc = *reinterpret_cast<const int2*>(anchor_loc + flat * 2);
            sum += (loc.x != loc.y) ? 1 : 0;
        }
        #pragma unroll
        for (int o = 16; o > 0; o >>= 1)
            sum += __shfl_down_sync(0xFFFFFFFFu, sum, o);

        int lane = threadIdx.x & 31;
        int wid  = threadIdx.x >> 5;
        if (lane == 0) rsm[wid] = sum;
        __syncthreads();
        if (threadIdx.x == 0) {
            int total = 0;
            #pragma unroll
            for (int i = 0; i < 8; i++) total += rsm[i];
            __stcs(out + off_len + batch, fmaxf((float)total, 1.0f));
            if (batch == 0 && off_scalar >= 0)
                __stcs(out + off_scalar, scalar_val);
        }
        return;
    }

    // ---- gather role ----
    __shared__ __align__(16) float s_stage[8][STAGES][PD]; // 16 KB
    __shared__ float s_label[CPB];
    __shared__ float s_mask [CPB];
    __shared__ float s_locx [CPB];
    __shared__ float s_locy [CPB];

    int wid  = threadIdx.x >> 5;
    int lane = threadIdx.x & 31;
    int cb   = (blockIdx.x - LEN_BLOCKS) * CPB;
    int c0   = cb + wid * ITER;

    // --- prologue: all 8 flats via one coalesced idx load + shuffles ---
    int val = 0;
    if (lane < 3 * ITER) val = cand_idx[3 * c0 + lane];

    // lane j (j<8) computes flat for candidate c0+j
    int bb = __shfl_sync(0xFFFFFFFFu, val, (lane < 8) ? 3 * lane + 0 : 0);
    int ww = __shfl_sync(0xFFFFFFFFu, val, (lane < 8) ? 3 * lane + 1 : 0);
    int aa = __shfl_sync(0xFFFFFFFFu, val, (lane < 8) ? 3 * lane + 2 : 0);
    long long myflat = (((long long)bb * PS + ww) * PA + aa);
    int flat_lo = (int)(myflat & 0xFFFFFFFFll);
    int flat_hi = (int)(myflat >> 32);

    uint32_t stage_base = (uint32_t)__cvta_generic_to_shared(&s_stage[wid][0][0]);

    // Issue first STAGES cp.async groups (flat[i] via shuffle from lane i).
    #pragma unroll
    for (int i = 0; i < STAGES; i++) {
        int lo = __shfl_sync(0xFFFFFFFFu, flat_lo, i);
        int hi = __shfl_sync(0xFFFFFFFFu, flat_hi, i);
        long long fl = ((long long)hi << 32) | (unsigned int)lo;
        const float* src = word_repr + fl * PD + lane * 4;
        cpasync16(stage_base + (uint32_t)(i * PD * 4) + lane * 16, src);
        cpcommit();
    }

    // loc/cls for my candidate (lanes 0..7), overlapping the cp.asyncs.
    float mymask = 0.0f;
    if (lane < ITER) {
        int2 loc = *reinterpret_cast<const int2*>(anchor_loc + myflat * 2);
        int  cls = anchor_cls[myflat];
        mymask = (loc.x != loc.y) ? 1.0f : 0.0f;
        int l = wid * ITER + lane;
        s_label[l] = (float)cls;
        s_mask [l] = mymask;
        s_locx [l] = (float)loc.x;
        s_locy [l] = (float)loc.y;
    }

    // --- main pipeline ---
    #pragma unroll
    for (int i = 0; i < ITER; i++) {
        cpwait3();                       // stage i complete
        int slot = i & (STAGES - 1);

        float mask = __shfl_sync(0xFFFFFFFFu, mymask, i);
        float4 t = *reinterpret_cast<float4*>(&s_stage[wid][slot][lane * 4]);
        t.x *= mask; t.y *= mask; t.z *= mask; t.w *= mask;
        __stcs(reinterpret_cast<float4*>(out + (long long)(c0 + i) * PD) + lane, t);

        if (i + STAGES < ITER) {
            int lo = __shfl_sync(0xFFFFFFFFu, flat_lo, i + STAGES);
            int hi = __shfl_sync(0xFFFFFFFFu, flat_hi, i + STAGES);
            long long fl = ((long long)hi << 32) | (unsigned int)lo;
            const float* src = word_repr + fl * PD + lane * 4;
            cpasync16(stage_base + (uint32_t)(slot * PD * 4) + lane * 16, src);
        }
        cpcommit();                      // empty commit in tail keeps count math fixed
    }
    cpwait0();

    __syncthreads();

    // Coalesced flush of the staged small outputs.
    int t = threadIdx.x;
    if (t < CPB) {
        __stcs(out + off_label + cb + t, s_label[t]);
        __stcs(out + off_mask  + cb + t, s_mask[t]);
    }
    if (t < 2 * CPB) {
        float v = (t & 1) ? s_locy[t >> 1] : s_locx[t >> 1];
        __stcs(out + off_loc + 2 * (long long)cb + t, v);
    }
}

// ---------------------------------------------------------------------------
// Host launcher
// ---------------------------------------------------------------------------
extern "C" void kernel_launch(void* const* d_in, const int* in_sizes, int n_in,
                              void* d_out, int out_size)
{
    const float* word_repr  = (const float*)d_in[0];  // (B,S,A,D) fp32
    const int*   anchor_cls = (const int*)d_in[1];    // (B,S,A)   int32
    const int*   anchor_loc = (const int*)d_in[2];    // (B,S,A,2) int32
    const int*   cand_idx   = (const int*)d_in[3];    // (B*C, 3)  int32
    float* out = (float*)d_out;

    int BC = in_sizes[3] / 3;          // 65536
    int C  = BC / PB;                  // 1024

    // Output tuple layout (reference return order):
    //   repr (B*C*D) | label (B*C) | [num (1)] | len (B) | mask (B*C) | loc (B*C*2)
    long long n_repr = (long long)BC * PD;
    long long total_with_scalar = n_repr + BC + 1 + PB + BC + 2LL * BC;

    long long off_label = n_repr;
    long long off_scalar, off_len;
    if ((long long)out_size >= total_with_scalar) {
        off_scalar = off_label + BC;
        off_len    = off_scalar + 1;
    } else {
        off_scalar = -1;
        off_len    = off_label + BC;
    }
    long long off_mask = off_len + PB;
    long long off_loc  = off_mask + BC;

    int threads = 256;                                        // 8 warps/block
    int blocks  = LEN_BLOCKS + (BC + CPB - 1) / CPB;          // 64 + 1024
    cand_kernel<<<blocks, threads>>>(word_repr, anchor_cls, anchor_loc,
                                     cand_idx, out,
                                     off_label, off_mask, off_loc,
                                     off_len, off_scalar,
                                     (float)C, BC, C);
}